// round 10
// baseline (speedup 1.0000x reference)
#include <cuda_runtime.h>
#include <cuda_bf16.h>
#include <math.h>
#include <stdint.h>

#define Tdim 1653
#define Ddim 512
#define Bdim 2
#define Edim 8
#define DE 64
#define BE 16
#define BT 3306
#define TDE (Tdim * DE)
#define KSPLIT 4
typedef __nv_bfloat16 bf16;
static const long long TT = (long long)Tdim * Tdim;

// ------------------- device scratch ------------------------------------------
__device__ float g_Y[3 * BT * Ddim];
__device__ float g_Wcat[3 * Ddim * Ddim];
__device__ float g_bcat[3 * Ddim];
__device__ float g_Q[BE * TDE], g_K[BE * TDE], g_V[BE * TDE];
__device__ float g_W2p[KSPLIT * BE * TDE];   // split-K partials
__device__ float g_W2[BE * TDE];             // W = orth^T @ V, [T,64]/head
__device__ float g_O[BE * TDE];
__device__ float g_X[BT * Ddim];

// ------------------- helpers -------------------------------------------------
__device__ __forceinline__ uint32_t smem_u32(const void* p) {
    uint32_t a;
    asm("{ .reg .u64 t; cvta.to.shared.u64 t, %1; cvt.u32.u64 %0, t; }"
        : "=r"(a) : "l"(p));
    return a;
}
__device__ __forceinline__ void sp2(float v, bf16& h, bf16& l) {
    h = __float2bfloat16(v);
    l = __float2bfloat16(v - __bfloat162float(h));
}
__device__ __forceinline__ void ldm4(uint32_t* r, uint32_t a) {
    asm volatile("ldmatrix.sync.aligned.m8n8.x4.shared.b16 {%0,%1,%2,%3}, [%4];"
        : "=r"(r[0]), "=r"(r[1]), "=r"(r[2]), "=r"(r[3]) : "r"(a));
}
__device__ __forceinline__ void ldm4t(uint32_t* r, uint32_t a) {
    asm volatile("ldmatrix.sync.aligned.m8n8.x4.trans.shared.b16 {%0,%1,%2,%3}, [%4];"
        : "=r"(r[0]), "=r"(r[1]), "=r"(r[2]), "=r"(r[3]) : "r"(a));
}
__device__ __forceinline__ void mma16816(float* d, const uint32_t* a, const uint32_t* b) {
    asm volatile("mma.sync.aligned.m16n8k16.row.col.f32.bf16.bf16.f32 "
        "{%0,%1,%2,%3}, {%4,%5,%6,%7}, {%8,%9}, {%0,%1,%2,%3};"
        : "+f"(d[0]), "+f"(d[1]), "+f"(d[2]), "+f"(d[3])
        : "r"(a[0]), "r"(a[1]), "r"(a[2]), "r"(a[3]), "r"(b[0]), "r"(b[1]));
}

__device__ __forceinline__ void cvt16(const float* __restrict__ s, bf16* hp, bf16* lp)
{
#pragma unroll
    for (int q = 0; q < 4; ++q) {
        float4 f = *reinterpret_cast<const float4*>(s + q * 4);
        bf16 h0, l0, h1, l1, h2, l2, h3, l3;
        sp2(f.x, h0, l0); sp2(f.y, h1, l1);
        sp2(f.z, h2, l2); sp2(f.w, h3, l3);
        __nv_bfloat162 a, b;
        a.x = h0; a.y = h1; b.x = h2; b.y = h3;
        reinterpret_cast<__nv_bfloat162*>(hp)[q * 2]     = a;
        reinterpret_cast<__nv_bfloat162*>(hp)[q * 2 + 1] = b;
        a.x = l0; a.y = l1; b.x = l2; b.y = l3;
        reinterpret_cast<__nv_bfloat162*>(lp)[q * 2]     = a;
        reinterpret_cast<__nv_bfloat162*>(lp)[q * 2 + 1] = b;
    }
}

// ---- tile loaders: fp32 gmem -> bf16 hi/lo smem ----
__device__ __forceinline__ void ld_nt(const float* __restrict__ src, int r0, int Rtot,
                                      int ld, int k0, int K, bf16* H, bf16* L)
{
    const int t = threadIdx.x;
    const int r = t >> 1, h = t & 1;
    const int kb = k0 + h * 16;
    bf16* hp = H + r * 40 + h * 16;
    bf16* lp = L + r * 40 + h * 16;
    const bool rowok = (r0 + r) < Rtot;
    const float* s = src + (long long)(r0 + r) * ld + kb;
    if (rowok && kb + 16 <= K && ((reinterpret_cast<uintptr_t>(s) & 15u) == 0)) {
        cvt16(s, hp, lp);
    } else {
#pragma unroll
        for (int q = 0; q < 16; ++q) {
            float v = (rowok && kb + q < K) ? s[q] : 0.f;
            sp2(v, hp[q], lp[q]);
        }
    }
}

template <int C>
__device__ __forceinline__ void ld_tr(const float* __restrict__ src, int k0, int K,
                                      int c0, int Ctot, int ld, bf16* H, bf16* L)
{
    constexpr int P  = C + 8;
    constexpr int CH = C / 16;
    const int t = threadIdx.x;
    if (t >= 32 * CH) return;
    const int kr = t / CH, mc = (t % CH) * 16;
    const bool rowok = (k0 + kr) < K;
    const float* s = src + (long long)(k0 + kr) * ld + c0 + mc;
    bf16* hp = H + kr * P + mc;
    bf16* lp = L + kr * P + mc;
    if (rowok && c0 + mc + 16 <= Ctot && ((reinterpret_cast<uintptr_t>(s) & 15u) == 0)) {
        cvt16(s, hp, lp);
    } else {
#pragma unroll
        for (int q = 0; q < 16; ++q) {
            float v = (rowok && c0 + mc + q < Ctot) ? s[q] : 0.f;
            sp2(v, hp[q], lp[q]);
        }
    }
}

// ------------------- split-bf16 tensor-core GEMM -----------------------------
// C[M,N] = A[M,K]*B^T (logical). TRA: A stored [k][m]; TRB: B stored [k][n].
// MODE 0: plain  1: +bias ep[n]  3: split-K partial store (blockIdx.x = k chunk)
template <int BN, int TRA, int TRB, int MODE>
__global__ void __launch_bounds__(256)
mma_gemm(const float* __restrict__ A, const float* __restrict__ B,
         float* __restrict__ C, int M, int N, int K,
         int lda, int ldb, int ldc,
         long long sA, long long sB, long long sC,
         const float* __restrict__ ep, long long sEp, float scale,
         int kItersPer, long long sKS)
{
    constexpr int PA  = TRA ? 136 : 40;
    constexpr int PB  = TRB ? (BN + 8) : 40;
    constexpr int ASZ = TRA ? 32 * 136 : 128 * 40;
    constexpr int BSZ = TRB ? 32 * (BN + 8) : BN * 40;
    __shared__ bf16 Ah[ASZ], Al[ASZ], Bh[BSZ], Bl[BSZ];

    const int bz = blockIdx.z;
    A += (long long)bz * sA;
    B += (long long)bz * sB;
    C += (long long)bz * sC;
    if (MODE == 3) C += (long long)blockIdx.x * sKS;
    if (MODE == 1) ep += (long long)bz * sEp;

    const int m0 = blockIdx.y * 128;
    const int n0 = (MODE == 3) ? 0 : blockIdx.x * BN;
    const int tid = threadIdx.x, l = tid & 31, wid = tid >> 5;
    constexpr int WN = BN / 2;
    constexpr int NT = WN / 8;
    const int wm = wid & 3, wn = wid >> 2;
    const int rmw = wm * 32;
    const int nbw = wn * WN;

    float acc[2][NT][4];
#pragma unroll
    for (int i = 0; i < 2; ++i)
#pragma unroll
        for (int j = 0; j < NT; ++j)
#pragma unroll
            for (int q = 0; q < 4; ++q) acc[i][j][q] = 0.f;

    const uint32_t baseAh = smem_u32(Ah), baseAl = smem_u32(Al);
    const uint32_t baseBh = smem_u32(Bh), baseBl = smem_u32(Bl);
    uint32_t aoff, boff;
    if (TRA) aoff = (((l & 7) + ((l >> 4) << 3)) * PA + ((l >> 3) & 1) * 8) * 2;
    else     aoff = ((l & 15) * PA + (l >> 4) * 8) * 2;
    if (TRB) boff = (((l & 7) + (((l >> 3) & 1) << 3)) * PB + ((l >> 4) << 3)) * 2;
    else     boff = (((l & 7) + ((l >> 4) << 3)) * PB + ((l >> 3) & 1) * 8) * 2;

    const int kItersAll = (K + 31) / 32;
    int kt0 = 0, kt1 = kItersAll;
    if (MODE == 3) {
        kt0 = blockIdx.x * kItersPer;
        kt1 = min(kItersAll, kt0 + kItersPer);
    }
    for (int kt = kt0; kt < kt1; ++kt) {
        const int k0 = kt * 32;
        if (TRA) ld_tr<128>(A, k0, K, m0, M, lda, Ah, Al);
        else     ld_nt(A, m0, M, lda, k0, K, Ah, Al);
        if (TRB) ld_tr<BN>(B, k0, K, n0, N, ldb, Bh, Bl);
        else     ld_nt(B, n0, N, ldb, k0, K, Bh, Bl);
        __syncthreads();
#pragma unroll
        for (int ks = 0; ks < 2; ++ks) {
            uint32_t ah[2][4], al2[2][4];
#pragma unroll
            for (int mt = 0; mt < 2; ++mt) {
                const int rm = rmw + mt * 16;
                const uint32_t rel = TRA ? (uint32_t)((ks * 16 * PA + rm) * 2)
                                         : (uint32_t)((rm * PA + ks * 16) * 2);
                if (TRA) { ldm4t(ah[mt], baseAh + rel + aoff); ldm4t(al2[mt], baseAl + rel + aoff); }
                else     { ldm4 (ah[mt], baseAh + rel + aoff); ldm4 (al2[mt], baseAl + rel + aoff); }
            }
            uint32_t bh[NT][2], bl2[NT][2];
#pragma unroll
            for (int np = 0; np < NT / 2; ++np) {
                const int nb = nbw + np * 16;
                const uint32_t rel = TRB ? (uint32_t)((ks * 16 * PB + nb) * 2)
                                         : (uint32_t)((nb * PB + ks * 16) * 2);
                uint32_t rh[4], rl[4];
                if (TRB) { ldm4t(rh, baseBh + rel + boff); ldm4t(rl, baseBl + rel + boff); }
                else     { ldm4 (rh, baseBh + rel + boff); ldm4 (rl, baseBl + rel + boff); }
                bh[2 * np][0] = rh[0]; bh[2 * np][1] = rh[1];
                bh[2 * np + 1][0] = rh[2]; bh[2 * np + 1][1] = rh[3];
                bl2[2 * np][0] = rl[0]; bl2[2 * np][1] = rl[1];
                bl2[2 * np + 1][0] = rl[2]; bl2[2 * np + 1][1] = rl[3];
            }
#pragma unroll
            for (int mt = 0; mt < 2; ++mt)
#pragma unroll
                for (int nt = 0; nt < NT; ++nt) {
                    mma16816(acc[mt][nt], ah[mt],  bh[nt]);
                    mma16816(acc[mt][nt], ah[mt],  bl2[nt]);
                    mma16816(acc[mt][nt], al2[mt], bh[nt]);
                }
        }
        __syncthreads();
    }

#pragma unroll
    for (int mt = 0; mt < 2; ++mt)
#pragma unroll
        for (int nt = 0; nt < NT; ++nt)
#pragma unroll
            for (int half = 0; half < 2; ++half) {
                const int m = m0 + rmw + mt * 16 + (l >> 2) + half * 8;
                const int n = n0 + nbw + nt * 8 + (l & 3) * 2;
                if (m >= M) continue;
                float v0 = acc[mt][nt][half * 2 + 0];
                float v1 = acc[mt][nt][half * 2 + 1];
                if (MODE == 1) {
                    if (n < N)     v0 += ep[n];
                    if (n + 1 < N) v1 += ep[n + 1];
                }
                if (n + 1 < N) {
                    *reinterpret_cast<float2*>(C + (long long)m * ldc + n) = make_float2(v0, v1);
                } else if (n < N) {
                    C[(long long)m * ldc + n] = v0;
                }
            }
}

// ------------------- fused attention: O = ((QK^T)*scale*punish) @ W2 ---------
// grid (13, BE), 256 threads, 128-row m-tile per CTA, s-loop of 128.
__global__ void __launch_bounds__(256)
fused_attn(const float* __restrict__ punish, float scale)
{
    extern __shared__ __align__(16) bf16 sm[];
    bf16* Qh = sm;               // [128][72]
    bf16* Ql = sm + 9216;
    bf16* Kh = sm + 18432;       // [128][72]
    bf16* Kl = sm + 27648;
    bf16* Wh = sm + 36864;       // [128][72]  (W2 s-tile, [s][d])
    bf16* Wl = sm + 46080;
    bf16* Ph = sm + 55296;       // [128][136]
    bf16* Pl = sm + 72704;

    const int g = blockIdx.y;
    const float* Qg = g_Q  + (long long)g * TDE;
    const float* Kg = g_K  + (long long)g * TDE;
    const float* Wg = g_W2 + (long long)g * TDE;
    float* Og = g_O + (long long)g * TDE;

    const int m0 = blockIdx.x * 128;
    const int tid = threadIdx.x, l = tid & 31, wid = tid >> 5;

    const uint32_t bQh = smem_u32(Qh), bQl = smem_u32(Ql);
    const uint32_t bKh = smem_u32(Kh), bKl = smem_u32(Kl);
    const uint32_t bWh = smem_u32(Wh), bWl = smem_u32(Wl);
    const uint32_t bPh = smem_u32(Ph), bPl = smem_u32(Pl);

    // load Q tile once
    {
        const int r = tid >> 1, c0 = (tid & 1) * 32;
        bf16* hp = Qh + r * 72 + c0;
        bf16* lp = Ql + r * 72 + c0;
        if (m0 + r < Tdim) {
            const float* s = Qg + (long long)(m0 + r) * DE + c0;
            cvt16(s, hp, lp);
            cvt16(s + 16, hp + 16, lp + 16);
        } else {
            const bf16 z = __float2bfloat16(0.f);
#pragma unroll
            for (int q = 0; q < 32; ++q) { hp[q] = z; lp[q] = z; }
        }
    }

    float acc2[8][4];
#pragma unroll
    for (int j = 0; j < 8; ++j)
#pragma unroll
        for (int q = 0; q < 4; ++q) acc2[j][q] = 0.f;

    // frag offsets
    const uint32_t aoffQ = ((l & 15) * 72 + (l >> 4) * 8) * 2;                          // A nt, P=72
    const uint32_t boffK = (((l & 7) + ((l >> 4) << 3)) * 72 + ((l >> 3) & 1) * 8) * 2; // B nt, P=72
    const uint32_t aoffP = ((l & 15) * 136 + (l >> 4) * 8) * 2;                         // A nt, P=136
    const uint32_t boffW = (((l & 7) + (((l >> 3) & 1) << 3)) * 72 + ((l >> 4) << 3)) * 2; // B tr, P=72

    const int wm = wid & 3, wn = wid >> 2;
    const int rmw = wm * 32, nbw = wn * 64;
    const int rm2 = wid * 16;

    for (int s0 = 0; s0 < Tdim; s0 += 128) {
        __syncthreads();     // protect K/W (prev mma) and Q load (first iter)
        // load K tile + W2 tile
        {
            const int r = tid >> 1, c0 = (tid & 1) * 32;
            bf16* khp = Kh + r * 72 + c0;
            bf16* klp = Kl + r * 72 + c0;
            bf16* whp = Wh + r * 72 + c0;
            bf16* wlp = Wl + r * 72 + c0;
            if (s0 + r < Tdim) {
                const float* sk = Kg + (long long)(s0 + r) * DE + c0;
                const float* sw = Wg + (long long)(s0 + r) * DE + c0;
                cvt16(sk, khp, klp);
                cvt16(sk + 16, khp + 16, klp + 16);
                cvt16(sw, whp, wlp);
                cvt16(sw + 16, whp + 16, wlp + 16);
            } else {
                const bf16 z = __float2bfloat16(0.f);
#pragma unroll
                for (int q = 0; q < 32; ++q) {
                    khp[q] = z; klp[q] = z; whp[q] = z; wlp[q] = z;
                }
            }
        }
        __syncthreads();

        // ---- mma1: P = Q K^T on this 128x128 tile ----
        {
            float acc[2][8][4];
#pragma unroll
            for (int i = 0; i < 2; ++i)
#pragma unroll
                for (int j = 0; j < 8; ++j)
#pragma unroll
                    for (int q = 0; q < 4; ++q) acc[i][j][q] = 0.f;
#pragma unroll
            for (int ks = 0; ks < 4; ++ks) {
                uint32_t ah[2][4], al[2][4];
#pragma unroll
                for (int mt = 0; mt < 2; ++mt) {
                    const uint32_t rel = (uint32_t)(((rmw + mt * 16) * 72 + ks * 16) * 2);
                    ldm4(ah[mt], bQh + rel + aoffQ);
                    ldm4(al[mt], bQl + rel + aoffQ);
                }
                uint32_t bh[8][2], bl[8][2];
#pragma unroll
                for (int np = 0; np < 4; ++np) {
                    const uint32_t rel = (uint32_t)(((nbw + np * 16) * 72 + ks * 16) * 2);
                    uint32_t rh[4], rl[4];
                    ldm4(rh, bKh + rel + boffK);
                    ldm4(rl, bKl + rel + boffK);
                    bh[2 * np][0] = rh[0]; bh[2 * np][1] = rh[1];
                    bh[2 * np + 1][0] = rh[2]; bh[2 * np + 1][1] = rh[3];
                    bl[2 * np][0] = rl[0]; bl[2 * np][1] = rl[1];
                    bl[2 * np + 1][0] = rl[2]; bl[2 * np + 1][1] = rl[3];
                }
#pragma unroll
                for (int mt = 0; mt < 2; ++mt)
#pragma unroll
                    for (int nt = 0; nt < 8; ++nt) {
                        mma16816(acc[mt][nt], ah[mt], bh[nt]);
                        mma16816(acc[mt][nt], ah[mt], bl[nt]);
                        mma16816(acc[mt][nt], al[mt], bh[nt]);
                    }
            }
            // punish * scale, split, store P to smem
#pragma unroll
            for (int mt = 0; mt < 2; ++mt)
#pragma unroll
                for (int nt = 0; nt < 8; ++nt)
#pragma unroll
                    for (int half = 0; half < 2; ++half) {
                        const int ml = rmw + mt * 16 + (l >> 2) + half * 8;
                        const int nl = nbw + nt * 8 + (l & 3) * 2;
                        const int mg = m0 + ml, sg = s0 + nl;
                        float v0 = acc[mt][nt][half * 2 + 0];
                        float v1 = acc[mt][nt][half * 2 + 1];
                        if (mg < Tdim && sg < Tdim)
                            v0 *= scale * punish[(long long)mg * Tdim + sg];
                        else v0 = 0.f;
                        if (mg < Tdim && sg + 1 < Tdim)
                            v1 *= scale * punish[(long long)mg * Tdim + sg + 1];
                        else v1 = 0.f;
                        bf16 h0, l0, h1, l1;
                        sp2(v0, h0, l0); sp2(v1, h1, l1);
                        __nv_bfloat162 hh, ll;
                        hh.x = h0; hh.y = h1; ll.x = l0; ll.y = l1;
                        *reinterpret_cast<__nv_bfloat162*>(Ph + ml * 136 + nl) = hh;
                        *reinterpret_cast<__nv_bfloat162*>(Pl + ml * 136 + nl) = ll;
                    }
        }
        __syncthreads();

        // ---- mma2: acc2 += P @ W2tile ----
#pragma unroll
        for (int ks2 = 0; ks2 < 8; ++ks2) {
            uint32_t ah[4], al[4];
            const uint32_t relA = (uint32_t)((rm2 * 136 + ks2 * 16) * 2);
            ldm4(ah, bPh + relA + aoffP);
            ldm4(al, bPl + relA + aoffP);
            uint32_t bh[8][2], bl[8][2];
#pragma unroll
            for (int np = 0; np < 4; ++np) {
                const uint32_t relB = (uint32_t)((ks2 * 16 * 72 + np * 16) * 2);
                uint32_t rh[4], rl[4];
                ldm4t(rh, bWh + relB + boffW);
                ldm4t(rl, bWl + relB + boffW);
                bh[2 * np][0] = rh[0]; bh[2 * np][1] = rh[1];
                bh[2 * np + 1][0] = rh[2]; bh[2 * np + 1][1] = rh[3];
                bl[2 * np][0] = rl[0]; bl[2 * np][1] = rl[1];
                bl[2 * np + 1][0] = rl[2]; bl[2 * np + 1][1] = rl[3];
            }
#pragma unroll
            for (int nt = 0; nt < 8; ++nt) {
                mma16816(acc2[nt], ah, bh[nt]);
                mma16816(acc2[nt], ah, bl[nt]);
                mma16816(acc2[nt], al, bh[nt]);
            }
        }
    }

    // epilogue: O[m][d]
#pragma unroll
    for (int nt = 0; nt < 8; ++nt)
#pragma unroll
        for (int half = 0; half < 2; ++half) {
            const int m = m0 + rm2 + (l >> 2) + half * 8;
            const int d = nt * 8 + (l & 3) * 2;
            if (m < Tdim)
                *reinterpret_cast<float2*>(Og + (long long)m * DE + d) =
                    make_float2(acc2[nt][half * 2 + 0], acc2[nt][half * 2 + 1]);
        }
}

// ------------------- elementwise kernels -------------------------------------
__global__ void pack_wb(const float* Wq, const float* Wk, const float* Wv,
                        const float* bq, const float* bk, const float* bv)
{
    const int i = blockIdx.x * 256 + threadIdx.x;
    const int WW = Ddim * Ddim;
    if (i < WW) {
        g_Wcat[i] = Wq[i];
        g_Wcat[WW + i] = Wk[i];
        g_Wcat[2 * WW + i] = Wv[i];
    }
    if (i < Ddim) {
        g_bcat[i] = bq[i];
        g_bcat[Ddim + i] = bk[i];
        g_bcat[2 * Ddim + i] = bv[i];
    }
}

__global__ void scatter_qkv()
{
    const int idx = blockIdx.x * 256 + threadIdx.x;
    if (idx >= BE * TDE) return;
    const int g = idx / TDE, f = idx % TDE;
    const int b = g >> 3, e = g & 7;
    const int tt = f % Tdim, j = f / Tdim;
    const long long src = (long long)(b * Tdim + tt) * Ddim + e * DE + j;
    const float yq = g_Y[src];
    const float yk = g_Y[(long long)BT * Ddim + src];
    const float yv = g_Y[2ll * BT * Ddim + src];
    g_Q[idx] = 1.2f / (1.f + expf(-1.6f * yq));
    g_K[idx] = 1.2f / (1.f + expf(-1.6f * yk));
    g_V[idx] = yv;
}

__global__ void reduce_w2()
{
    const int N4 = BE * TDE / 4;
    const int i = blockIdx.x * 256 + threadIdx.x;
    if (i >= N4) return;
    const float4* p = reinterpret_cast<const float4*>(g_W2p);
    float4 a = p[i];
    float4 b = p[N4 + i];
    float4 c = p[2 * N4 + i];
    float4 d = p[3 * N4 + i];
    float4 r;
    r.x = a.x + b.x + c.x + d.x;
    r.y = a.y + b.y + c.y + d.y;
    r.z = a.z + b.z + c.z + d.z;
    r.w = a.w + b.w + c.w + d.w;
    reinterpret_cast<float4*>(g_W2)[i] = r;
}

__global__ void gather_x()
{
    const int idx = blockIdx.x * 256 + threadIdx.x;
    if (idx >= BT * Ddim) return;
    const int b = idx / (Tdim * Ddim);
    const int rem = idx % (Tdim * Ddim);
    const int t = rem / Ddim, d = rem % Ddim;
    const int g = b * Edim + (d >> 6);
    g_X[idx] = g_O[((long long)g * Tdim + t) * DE + (d & 63)];
}

// ------------------- launch --------------------------------------------------
extern "C" void kernel_launch(void* const* d_in, const int* in_sizes, int n_in,
                              void* d_out, int out_size)
{
    const float* input  = (const float*)d_in[0];
    const float* Wq     = (const float*)d_in[1];
    const float* bq     = (const float*)d_in[2];
    const float* Wk     = (const float*)d_in[3];
    const float* bk     = (const float*)d_in[4];
    const float* Wv     = (const float*)d_in[5];
    const float* bv     = (const float*)d_in[6];
    const float* Wo     = (const float*)d_in[7];
    const float* bo     = (const float*)d_in[8];
    const float* punish = (const float*)d_in[9];
    const float* orth   = (const float*)d_in[10];
    float* out = (float*)d_out;

    float *Y, *Wcat, *bcat, *Q, *Kp, *V, *W2p, *W2, *O, *X;
    cudaGetSymbolAddress((void**)&Y,    g_Y);
    cudaGetSymbolAddress((void**)&Wcat, g_Wcat);
    cudaGetSymbolAddress((void**)&bcat, g_bcat);
    cudaGetSymbolAddress((void**)&Q,    g_Q);
    cudaGetSymbolAddress((void**)&Kp,   g_K);
    cudaGetSymbolAddress((void**)&V,    g_V);
    cudaGetSymbolAddress((void**)&W2p,  g_W2p);
    cudaGetSymbolAddress((void**)&W2,   g_W2);
    cudaGetSymbolAddress((void**)&O,    g_O);
    cudaGetSymbolAddress((void**)&X,    g_X);

    const float inv_sqrt_T = 1.0f / sqrtf((float)Tdim);
    const int WW = Ddim * Ddim;
    const int FUSED_SMEM = 180224;
    static bool attr_done = false;
    if (!attr_done) {
        cudaFuncSetAttribute(fused_attn, cudaFuncAttributeMaxDynamicSharedMemorySize,
                             FUSED_SMEM);
        attr_done = true;
    }

    // 0) pack Q/K/V weights for one fused launch
    pack_wb<<<(WW + 255) / 256, 256>>>(Wq, Wk, Wv, bq, bk, bv);

    // 1) projections: Y[z] = input @ W[z]^T + b[z]
    mma_gemm<128, 0, 0, 1><<<dim3(4, 26, 3), 256>>>(
        input, Wcat, Y, BT, Ddim, Ddim, Ddim, Ddim, Ddim,
        0ll, (long long)WW, (long long)BT * Ddim, bcat, (long long)Ddim, 0.f, 0, 0ll);

    // 2) reshape + sigmoid
    scatter_qkv<<<(BE * TDE + 255) / 256, 256>>>();

    // 3) W2 partials = orth^T @ V  (split-K x4), then reduce
    mma_gemm<64, 1, 1, 3><<<dim3(KSPLIT, 13, BE), 256>>>(
        orth, V, W2p, Tdim, DE, Tdim, Tdim, DE, DE,
        TT, (long long)TDE, (long long)TDE, nullptr, 0ll, 0.f,
        13, (long long)BE * TDE);
    reduce_w2<<<(BE * TDE / 4 + 255) / 256, 256>>>();

    // 4+5) fused: O = ((Q K^T) * scale * punish) @ W2
    fused_attn<<<dim3(13, BE), 256, FUSED_SMEM>>>(punish, inv_sqrt_T);

    // 6) inverse reshape
    gather_x<<<(BT * Ddim + 255) / 256, 256>>>();

    // 7) out = X @ Wo^T + bo
    mma_gemm<128, 0, 0, 1><<<dim3(4, 26, 1), 256>>>(
        X, Wo, out, BT, Ddim, Ddim, Ddim, Ddim, Ddim,
        0ll, 0ll, 0ll, bo, 0ll, 0.f, 0, 0ll);
}

// round 12
// speedup vs baseline: 1.0253x; 1.0253x over previous
#include <cuda_runtime.h>
#include <cuda_bf16.h>
#include <math.h>
#include <stdint.h>

#define Tdim 1653
#define TSP  1664
#define Ddim 512
#define Bdim 2
#define Edim 8
#define DE 64
#define BE 16
#define BT 3306
#define TDE (Tdim * DE)
#define KSPLIT 4
typedef __nv_bfloat16 bf16;
static const long long TT = (long long)Tdim * Tdim;

// ------------------- device scratch ------------------------------------------
__device__ float g_Y[3 * BT * Ddim];
__device__ float g_Wcat[3 * Ddim * Ddim];
__device__ float g_bcat[3 * Ddim];
__device__ float g_Q[BE * TDE], g_K[BE * TDE], g_V[BE * TDE];
__device__ float g_W2p[KSPLIT * BE * TDE];
__device__ float g_W2[BE * TDE];
__device__ float g_S[(long long)BE * Tdim * TSP];   // S fp32, padded stride
__device__ float g_Op[KSPLIT * BE * TDE];
__device__ float g_O[BE * TDE];
__device__ float g_X[BT * Ddim];

// ------------------- helpers -------------------------------------------------
__device__ __forceinline__ uint32_t smem_u32(const void* p) {
    uint32_t a;
    asm("{ .reg .u64 t; cvta.to.shared.u64 t, %1; cvt.u32.u64 %0, t; }"
        : "=r"(a) : "l"(p));
    return a;
}
__device__ __forceinline__ void sp2(float v, bf16& h, bf16& l) {
    h = __float2bfloat16(v);
    l = __float2bfloat16(v - __bfloat162float(h));
}
__device__ __forceinline__ void ldm4(uint32_t* r, uint32_t a) {
    asm volatile("ldmatrix.sync.aligned.m8n8.x4.shared.b16 {%0,%1,%2,%3}, [%4];"
        : "=r"(r[0]), "=r"(r[1]), "=r"(r[2]), "=r"(r[3]) : "r"(a));
}
__device__ __forceinline__ void ldm4t(uint32_t* r, uint32_t a) {
    asm volatile("ldmatrix.sync.aligned.m8n8.x4.trans.shared.b16 {%0,%1,%2,%3}, [%4];"
        : "=r"(r[0]), "=r"(r[1]), "=r"(r[2]), "=r"(r[3]) : "r"(a));
}
__device__ __forceinline__ void mma16816(float* d, const uint32_t* a, const uint32_t* b) {
    asm volatile("mma.sync.aligned.m16n8k16.row.col.f32.bf16.bf16.f32 "
        "{%0,%1,%2,%3}, {%4,%5,%6,%7}, {%8,%9}, {%0,%1,%2,%3};"
        : "+f"(d[0]), "+f"(d[1]), "+f"(d[2]), "+f"(d[3])
        : "r"(a[0]), "r"(a[1]), "r"(a[2]), "r"(a[3]), "r"(b[0]), "r"(b[1]));
}

__device__ __forceinline__ void cvt16(const float* __restrict__ s, bf16* hp, bf16* lp)
{
#pragma unroll
    for (int q = 0; q < 4; ++q) {
        float4 f = *reinterpret_cast<const float4*>(s + q * 4);
        bf16 h0, l0, h1, l1, h2, l2, h3, l3;
        sp2(f.x, h0, l0); sp2(f.y, h1, l1);
        sp2(f.z, h2, l2); sp2(f.w, h3, l3);
        __nv_bfloat162 a, b;
        a.x = h0; a.y = h1; b.x = h2; b.y = h3;
        reinterpret_cast<__nv_bfloat162*>(hp)[q * 2]     = a;
        reinterpret_cast<__nv_bfloat162*>(hp)[q * 2 + 1] = b;
        a.x = l0; a.y = l1; b.x = l2; b.y = l3;
        reinterpret_cast<__nv_bfloat162*>(lp)[q * 2]     = a;
        reinterpret_cast<__nv_bfloat162*>(lp)[q * 2 + 1] = b;
    }
}

// ---- tile loaders ----
// fp32, no-trans: 128 rows x 32 k, pitch 40
__device__ __forceinline__ void ld_nt(const float* __restrict__ src, int r0, int Rtot,
                                      int ld, int k0, int K, bf16* H, bf16* L)
{
    const int t = threadIdx.x;
    const int r = t >> 1, h = t & 1;
    const int kb = k0 + h * 16;
    bf16* hp = H + r * 40 + h * 16;
    bf16* lp = L + r * 40 + h * 16;
    const bool rowok = (r0 + r) < Rtot;
    const float* s = src + (long long)(r0 + r) * ld + kb;
    if (rowok && kb + 16 <= K && ((reinterpret_cast<uintptr_t>(s) & 15u) == 0)) {
        cvt16(s, hp, lp);
    } else {
#pragma unroll
        for (int q = 0; q < 16; ++q) {
            float v = (rowok && kb + q < K) ? s[q] : 0.f;
            sp2(v, hp[q], lp[q]);
        }
    }
}

// fp32, trans, COALESCED: 32 k-rows x C cols, pitch C+8
template <int C>
__device__ __forceinline__ void ld_tr(const float* __restrict__ src, int k0, int K,
                                      int c0, int Ctot, int ld, bf16* H, bf16* L)
{
    constexpr int P = C + 8;
    const int t = threadIdx.x;
#pragma unroll
    for (int j = t; j < 32 * C; j += 256) {
        const int kr = j / C, c = j % C;
        float v = 0.f;
        if (k0 + kr < K && c0 + c < Ctot)
            v = src[(long long)(k0 + kr) * ld + c0 + c];
        sp2(v, H[kr * P + c], L[kr * P + c]);
    }
}

// ------------------- split-bf16 tensor-core GEMM -----------------------------
// C[M,N] = A[M,K]*B^T (logical). TRA: A stored [k][m]; TRB: B stored [k][n].
// MODE 0: plain fp32 out        MODE 1: +bias ep[n] fp32 out
// MODE 2: *scale*ep[m*Tdim+n] fp32 out (punish; ldc = padded stride)
// MODE 3: split-K partial fp32 out (blockIdx.x = k chunk, n0 = 0)
template <int BN, int TRA, int TRB, int MODE>
__global__ void __launch_bounds__(256)
mma_gemm(const float* __restrict__ A, const float* __restrict__ B,
         float* __restrict__ C, int M, int N, int K,
         int lda, int ldb, int ldc,
         long long sA, long long sB, long long sC,
         const float* __restrict__ ep, long long sEp, float scale,
         int kItersPer, long long sKS)
{
    constexpr int PA  = TRA ? 136 : 40;
    constexpr int PB  = TRB ? (BN + 8) : 40;
    constexpr int ASZ = TRA ? 32 * 136 : 128 * 40;
    constexpr int BSZ = TRB ? 32 * (BN + 8) : BN * 40;
    __shared__ bf16 Ah[ASZ], Al[ASZ], Bh[BSZ], Bl[BSZ];

    const int bz = blockIdx.z;
    A += (long long)bz * sA;
    B += (long long)bz * sB;
    C += (long long)bz * sC;
    if (MODE == 3) C += (long long)blockIdx.x * sKS;
    if (MODE == 1 || MODE == 2) ep += (long long)bz * sEp;

    const int m0 = blockIdx.y * 128;
    const int n0 = (MODE == 3) ? 0 : blockIdx.x * BN;
    const int tid = threadIdx.x, l = tid & 31, wid = tid >> 5;
    constexpr int WN = BN / 2;
    constexpr int NT = WN / 8;
    const int wm = wid & 3, wn = wid >> 2;
    const int rmw = wm * 32;
    const int nbw = wn * WN;

    float acc[2][NT][4];
#pragma unroll
    for (int i = 0; i < 2; ++i)
#pragma unroll
        for (int j = 0; j < NT; ++j)
#pragma unroll
            for (int q = 0; q < 4; ++q) acc[i][j][q] = 0.f;

    const uint32_t baseAh = smem_u32(Ah), baseAl = smem_u32(Al);
    const uint32_t baseBh = smem_u32(Bh), baseBl = smem_u32(Bl);
    uint32_t aoff, boff;
    if (TRA) aoff = (((l & 7) + ((l >> 4) << 3)) * PA + ((l >> 3) & 1) * 8) * 2;
    else     aoff = ((l & 15) * PA + (l >> 4) * 8) * 2;
    if (TRB) boff = (((l & 7) + (((l >> 3) & 1) << 3)) * PB + ((l >> 4) << 3)) * 2;
    else     boff = (((l & 7) + ((l >> 4) << 3)) * PB + ((l >> 3) & 1) * 8) * 2;

    const int kItersAll = (K + 31) / 32;
    int kt0 = 0, kt1 = kItersAll;
    if (MODE == 3) {
        kt0 = blockIdx.x * kItersPer;
        kt1 = min(kItersAll, kt0 + kItersPer);
    }
    for (int kt = kt0; kt < kt1; ++kt) {
        const int k0 = kt * 32;
        if (TRA) ld_tr<128>(A, k0, K, m0, M, lda, Ah, Al);
        else     ld_nt(A, m0, M, lda, k0, K, Ah, Al);
        if (TRB) ld_tr<BN>(B, k0, K, n0, N, ldb, Bh, Bl);
        else     ld_nt(B, n0, N, ldb, k0, K, Bh, Bl);
        __syncthreads();
#pragma unroll
        for (int ks = 0; ks < 2; ++ks) {
            uint32_t ah[2][4], al2[2][4];
#pragma unroll
            for (int mt = 0; mt < 2; ++mt) {
                const int rm = rmw + mt * 16;
                const uint32_t rel = TRA ? (uint32_t)((ks * 16 * PA + rm) * 2)
                                         : (uint32_t)((rm * PA + ks * 16) * 2);
                if (TRA) { ldm4t(ah[mt], baseAh + rel + aoff); ldm4t(al2[mt], baseAl + rel + aoff); }
                else     { ldm4 (ah[mt], baseAh + rel + aoff); ldm4 (al2[mt], baseAl + rel + aoff); }
            }
            uint32_t bh[NT][2], bl2[NT][2];
#pragma unroll
            for (int np = 0; np < NT / 2; ++np) {
                const int nb = nbw + np * 16;
                const uint32_t rel = TRB ? (uint32_t)((ks * 16 * PB + nb) * 2)
                                         : (uint32_t)((nb * PB + ks * 16) * 2);
                uint32_t rh[4], rl[4];
                if (TRB) { ldm4t(rh, baseBh + rel + boff); ldm4t(rl, baseBl + rel + boff); }
                else     { ldm4 (rh, baseBh + rel + boff); ldm4 (rl, baseBl + rel + boff); }
                bh[2 * np][0] = rh[0]; bh[2 * np][1] = rh[1];
                bh[2 * np + 1][0] = rh[2]; bh[2 * np + 1][1] = rh[3];
                bl2[2 * np][0] = rl[0]; bl2[2 * np][1] = rl[1];
                bl2[2 * np + 1][0] = rl[2]; bl2[2 * np + 1][1] = rl[3];
            }
#pragma unroll
            for (int mt = 0; mt < 2; ++mt)
#pragma unroll
                for (int nt = 0; nt < NT; ++nt) {
                    mma16816(acc[mt][nt], ah[mt],  bh[nt]);
                    mma16816(acc[mt][nt], ah[mt],  bl2[nt]);
                    mma16816(acc[mt][nt], al2[mt], bh[nt]);
                }
        }
        __syncthreads();
    }

#pragma unroll
    for (int mt = 0; mt < 2; ++mt)
#pragma unroll
        for (int nt = 0; nt < NT; ++nt)
#pragma unroll
            for (int half = 0; half < 2; ++half) {
                const int m = m0 + rmw + mt * 16 + (l >> 2) + half * 8;
                const int n = n0 + nbw + nt * 8 + (l & 3) * 2;
                if (m >= M) continue;
                float v0 = acc[mt][nt][half * 2 + 0];
                float v1 = acc[mt][nt][half * 2 + 1];
                if (MODE == 1) {
                    if (n < N)     v0 += ep[n];
                    if (n + 1 < N) v1 += ep[n + 1];
                }
                if (MODE == 2) {
                    if (n < N)     v0 *= scale * ep[(long long)m * Tdim + n];
                    if (n + 1 < N) v1 *= scale * ep[(long long)m * Tdim + n + 1];
                }
                if (n + 1 < N) {
                    *reinterpret_cast<float2*>(C + (long long)m * ldc + n) = make_float2(v0, v1);
                } else if (n < N) {
                    C[(long long)m * ldc + n] = v0;
                }
            }
}

// ------------------- elementwise kernels -------------------------------------
__global__ void pack_wb(const float* Wq, const float* Wk, const float* Wv,
                        const float* bq, const float* bk, const float* bv)
{
    const int i = blockIdx.x * 256 + threadIdx.x;
    const int WW = Ddim * Ddim;
    if (i < WW) {
        g_Wcat[i] = Wq[i];
        g_Wcat[WW + i] = Wk[i];
        g_Wcat[2 * WW + i] = Wv[i];
    }
    if (i < Ddim) {
        g_bcat[i] = bq[i];
        g_bcat[Ddim + i] = bk[i];
        g_bcat[2 * Ddim + i] = bv[i];
    }
}

__global__ void scatter_qkv()
{
    const int idx = blockIdx.x * 256 + threadIdx.x;
    if (idx >= BE * TDE) return;
    const int g = idx / TDE, f = idx % TDE;
    const int b = g >> 3, e = g & 7;
    const int tt = f % Tdim, j = f / Tdim;
    const long long src = (long long)(b * Tdim + tt) * Ddim + e * DE + j;
    const float yq = g_Y[src];
    const float yk = g_Y[(long long)BT * Ddim + src];
    const float yv = g_Y[2ll * BT * Ddim + src];
    g_Q[idx] = 1.2f / (1.f + expf(-1.6f * yq));
    g_K[idx] = 1.2f / (1.f + expf(-1.6f * yk));
    g_V[idx] = yv;
}

__global__ void reduce4(const float* __restrict__ src, float* __restrict__ dst)
{
    const int N4 = BE * TDE / 4;
    const int i = blockIdx.x * 256 + threadIdx.x;
    if (i >= N4) return;
    const float4* p = reinterpret_cast<const float4*>(src);
    float4 a = p[i];
    float4 b = p[N4 + i];
    float4 c = p[2 * N4 + i];
    float4 d = p[3 * N4 + i];
    float4 r;
    r.x = a.x + b.x + c.x + d.x;
    r.y = a.y + b.y + c.y + d.y;
    r.z = a.z + b.z + c.z + d.z;
    r.w = a.w + b.w + c.w + d.w;
    reinterpret_cast<float4*>(dst)[i] = r;
}

__global__ void gather_x()
{
    const int idx = blockIdx.x * 256 + threadIdx.x;
    if (idx >= BT * Ddim) return;
    const int b = idx / (Tdim * Ddim);
    const int rem = idx % (Tdim * Ddim);
    const int t = rem / Ddim, d = rem % Ddim;
    const int g = b * Edim + (d >> 6);
    g_X[idx] = g_O[((long long)g * Tdim + t) * DE + (d & 63)];
}

// ------------------- launch --------------------------------------------------
extern "C" void kernel_launch(void* const* d_in, const int* in_sizes, int n_in,
                              void* d_out, int out_size)
{
    const float* input  = (const float*)d_in[0];
    const float* Wq     = (const float*)d_in[1];
    const float* bq     = (const float*)d_in[2];
    const float* Wk     = (const float*)d_in[3];
    const float* bk     = (const float*)d_in[4];
    const float* Wv     = (const float*)d_in[5];
    const float* bv     = (const float*)d_in[6];
    const float* Wo     = (const float*)d_in[7];
    const float* bo     = (const float*)d_in[8];
    const float* punish = (const float*)d_in[9];
    const float* orth   = (const float*)d_in[10];
    float* out = (float*)d_out;

    float *Y, *Wcat, *bcat, *Q, *Kp, *V, *W2p, *W2, *S, *Op, *O, *X;
    cudaGetSymbolAddress((void**)&Y,    g_Y);
    cudaGetSymbolAddress((void**)&Wcat, g_Wcat);
    cudaGetSymbolAddress((void**)&bcat, g_bcat);
    cudaGetSymbolAddress((void**)&Q,    g_Q);
    cudaGetSymbolAddress((void**)&Kp,   g_K);
    cudaGetSymbolAddress((void**)&V,    g_V);
    cudaGetSymbolAddress((void**)&W2p,  g_W2p);
    cudaGetSymbolAddress((void**)&W2,   g_W2);
    cudaGetSymbolAddress((void**)&S,    g_S);
    cudaGetSymbolAddress((void**)&Op,   g_Op);
    cudaGetSymbolAddress((void**)&O,    g_O);
    cudaGetSymbolAddress((void**)&X,    g_X);

    const float inv_sqrt_T = 1.0f / sqrtf((float)Tdim);
    const int WW = Ddim * Ddim;

    // 0) pack Q/K/V weights
    pack_wb<<<(WW + 255) / 256, 256>>>(Wq, Wk, Wv, bq, bk, bv);

    // 1) projections: Y[z] = input @ W[z]^T + b[z]
    mma_gemm<128, 0, 0, 1><<<dim3(4, 26, 3), 256>>>(
        input, Wcat, Y, BT, Ddim, Ddim, Ddim, Ddim, Ddim,
        0ll, (long long)WW, (long long)BT * Ddim, bcat, (long long)Ddim, 0.f, 0, 0ll);

    // 2) reshape + sigmoid
    scatter_qkv<<<(BE * TDE + 255) / 256, 256>>>();

    // 3) W2 partials = orth^T @ V  (split-K x4, coalesced loaders), reduce
    mma_gemm<64, 1, 1, 3><<<dim3(KSPLIT, 13, BE), 256>>>(
        orth, V, W2p, Tdim, DE, Tdim, Tdim, DE, DE,
        TT, (long long)TDE, (long long)TDE, nullptr, 0ll, 0.f,
        13, (long long)BE * TDE);
    reduce4<<<(BE * TDE / 4 + 255) / 256, 256>>>(W2p, W2);

    // 4) S = (Q K^T) * scale * punish  -> fp32, padded stride TSP
    mma_gemm<128, 0, 0, 2><<<dim3(13, 13, BE), 256>>>(
        Q, Kp, S, Tdim, Tdim, DE, DE, DE, TSP,
        (long long)TDE, (long long)TDE, (long long)Tdim * TSP,
        punish, 0ll, inv_sqrt_T, 0, 0ll);

    // 5) O partials = S @ W2  (split-K x4), reduce
    mma_gemm<64, 0, 1, 3><<<dim3(KSPLIT, 13, BE), 256>>>(
        S, W2, Op, Tdim, DE, Tdim, TSP, DE, DE,
        (long long)Tdim * TSP, (long long)TDE, (long long)TDE, nullptr, 0ll, 0.f,
        13, (long long)BE * TDE);
    reduce4<<<(BE * TDE / 4 + 255) / 256, 256>>>(Op, O);

    // 6) inverse reshape
    gather_x<<<(BT * Ddim + 255) / 256, 256>>>();

    // 7) out = X @ Wo^T + bo
    mma_gemm<128, 0, 0, 1><<<dim3(4, 26, 1), 256>>>(
        X, Wo, out, BT, Ddim, Ddim, Ddim, Ddim, Ddim,
        0ll, 0ll, 0ll, bo, 0ll, 0.f, 0, 0ll);
}

// round 13
// speedup vs baseline: 1.2735x; 1.2420x over previous
#include <cuda_runtime.h>
#include <cuda_bf16.h>
#include <math.h>
#include <stdint.h>

#define Tdim 1653
#define TSP  1664
#define Ddim 512
#define Bdim 2
#define Edim 8
#define DE 64
#define BE 16
#define BT 3306
#define TDE (Tdim * DE)
#define KSPLIT 8
typedef __nv_bfloat16 bf16;
static const long long TT = (long long)Tdim * Tdim;

// ------------------- device scratch ------------------------------------------
__device__ __align__(16) float g_Y[3 * BT * Ddim];
__device__ __align__(16) float g_Wcat[3 * Ddim * Ddim];
__device__ __align__(16) float g_bcat[3 * Ddim];
__device__ __align__(16) float g_Q[BE * TDE], g_K[BE * TDE], g_V[BE * TDE];
__device__ __align__(16) float g_W2p[KSPLIT * BE * TDE];
__device__ __align__(16) float g_W2[BE * TDE];
__device__ __align__(16) float g_S[(long long)BE * Tdim * TSP];
__device__ __align__(16) float g_Op[KSPLIT * BE * TDE];
__device__ __align__(16) float g_O[BE * TDE];
__device__ __align__(16) float g_X[BT * Ddim];

// ------------------- helpers -------------------------------------------------
__device__ __forceinline__ uint32_t smem_u32(const void* p) {
    uint32_t a;
    asm("{ .reg .u64 t; cvta.to.shared.u64 t, %1; cvt.u32.u64 %0, t; }"
        : "=r"(a) : "l"(p));
    return a;
}
__device__ __forceinline__ void sp2(float v, bf16& h, bf16& l) {
    h = __float2bfloat16(v);
    l = __float2bfloat16(v - __bfloat162float(h));
}
__device__ __forceinline__ void ldm4(uint32_t* r, uint32_t a) {
    asm volatile("ldmatrix.sync.aligned.m8n8.x4.shared.b16 {%0,%1,%2,%3}, [%4];"
        : "=r"(r[0]), "=r"(r[1]), "=r"(r[2]), "=r"(r[3]) : "r"(a));
}
__device__ __forceinline__ void ldm4t(uint32_t* r, uint32_t a) {
    asm volatile("ldmatrix.sync.aligned.m8n8.x4.trans.shared.b16 {%0,%1,%2,%3}, [%4];"
        : "=r"(r[0]), "=r"(r[1]), "=r"(r[2]), "=r"(r[3]) : "r"(a));
}
__device__ __forceinline__ void mma16816(float* d, const uint32_t* a, const uint32_t* b) {
    asm volatile("mma.sync.aligned.m16n8k16.row.col.f32.bf16.bf16.f32 "
        "{%0,%1,%2,%3}, {%4,%5,%6,%7}, {%8,%9}, {%0,%1,%2,%3};"
        : "+f"(d[0]), "+f"(d[1]), "+f"(d[2]), "+f"(d[3])
        : "r"(a[0]), "r"(a[1]), "r"(a[2]), "r"(a[3]), "r"(b[0]), "r"(b[1]));
}

// ---- cp.async prefetchers: fp32 gmem -> fp32 staging smem ----
// no-trans: 128 rows x 32 k, staging pitch 36 floats (dst 16B aligned per chunk)
__device__ __forceinline__ void pf_nt(const float* __restrict__ src, int r0, int Rtot,
                                      int ld, int k0, int K, float* st)
{
    const int t = threadIdx.x;
    const int r = t >> 1, h = t & 1;
    const int kb = k0 + h * 16;
    float* d = st + r * 36 + h * 16;
    const float* s = src + (long long)(r0 + r) * ld + kb;
    if ((r0 + r) < Rtot) {
        const uint32_t da = smem_u32(d);
#pragma unroll
        for (int q = 0; q < 4; ++q) {
            const int rem = (K - (kb + q * 4)) * 4;
            if (rem >= 16) {
                asm volatile("cp.async.ca.shared.global [%0], [%1], 16;"
                             :: "r"(da + q * 16), "l"(s + q * 4));
            } else if (rem > 0) {
                asm volatile("cp.async.ca.shared.global [%0], [%1], 16, %2;"
                             :: "r"(da + q * 16), "l"(s + q * 4), "r"(rem));
            } else {
                *reinterpret_cast<float4*>(d + q * 4) = make_float4(0.f, 0.f, 0.f, 0.f);
            }
        }
    } else {
#pragma unroll
        for (int q = 0; q < 4; ++q)
            *reinterpret_cast<float4*>(d + q * 4) = make_float4(0.f, 0.f, 0.f, 0.f);
    }
}

// trans: 32 k-rows x C cols, staging pitch C+1 floats, 4-byte cp.async (any stride)
template <int C>
__device__ __forceinline__ void pf_tr(const float* __restrict__ src, int k0, int K,
                                      int c0, int Ctot, int ld, float* st)
{
    const int t = threadIdx.x;
#pragma unroll
    for (int j = t; j < 32 * C; j += 256) {
        const int kr = j / C, c = j % C;
        float* d = st + kr * (C + 1) + c;
        if (k0 + kr < K && c0 + c < Ctot) {
            asm volatile("cp.async.ca.shared.global [%0], [%1], 4;"
                         :: "r"(smem_u32(d)),
                            "l"(src + (long long)(k0 + kr) * ld + c0 + c));
        } else {
            *d = 0.f;
        }
    }
}

// ---- converters: fp32 staging -> bf16 hi/lo tiles ----
__device__ __forceinline__ void cvt_nt(const float* st, bf16* H, bf16* L)
{
    const int t = threadIdx.x;
    const int r = t >> 1, h = t & 1;
    const float* s = st + r * 36 + h * 16;
    bf16* hp = H + r * 40 + h * 16;
    bf16* lp = L + r * 40 + h * 16;
#pragma unroll
    for (int q = 0; q < 16; q += 2) {
        bf16 h0, l0, h1, l1;
        sp2(s[q], h0, l0); sp2(s[q + 1], h1, l1);
        __nv_bfloat162 hh; hh.x = h0; hh.y = h1;
        __nv_bfloat162 ll; ll.x = l0; ll.y = l1;
        *reinterpret_cast<__nv_bfloat162*>(hp + q) = hh;
        *reinterpret_cast<__nv_bfloat162*>(lp + q) = ll;
    }
}

template <int C, int P>
__device__ __forceinline__ void cvt_tr(const float* st, bf16* H, bf16* L)
{
    const int t = threadIdx.x;
#pragma unroll
    for (int j = t; j < 32 * C; j += 256) {
        const int kr = j / C, c = j % C;
        bf16 h, l;
        sp2(st[kr * (C + 1) + c], h, l);
        H[kr * P + c] = h;
        L[kr * P + c] = l;
    }
}

// ------------------- pipelined split-bf16 tensor-core GEMM -------------------
// C[M,N] = A[M,K]*B^T (logical). TRA: A stored [k][m]; TRB: B stored [k][n].
// MODE 1: +bias ep[n]  MODE 2: *scale*ep[m*Tdim+n]  MODE 3: split-K partial
template <int BN, int TRA, int TRB, int MODE>
__global__ void __launch_bounds__(256, 2)
mma_gemm(const float* __restrict__ A, const float* __restrict__ B,
         float* __restrict__ C, int M, int N, int K,
         int lda, int ldb, int ldc,
         long long sA, long long sB, long long sC,
         const float* __restrict__ ep, long long sEp, float scale,
         int kItersPer, long long sKS)
{
    constexpr int PA  = TRA ? 136 : 40;
    constexpr int PB  = TRB ? (BN + 8) : 40;
    constexpr int ASZ = TRA ? 32 * 136 : 128 * 40;
    constexpr int BSZ = TRB ? 32 * (BN + 8) : BN * 40;
    constexpr int SAF = TRA ? 32 * 129 : 128 * 36;
    constexpr int SBF = TRB ? 32 * (BN + 1) : BN * 36;

    extern __shared__ __align__(16) char smraw[];
    float* stA0 = reinterpret_cast<float*>(smraw);
    float* stA1 = stA0 + SAF;
    float* stB0 = stA1 + SAF;
    float* stB1 = stB0 + SBF;
    bf16*  Ah   = reinterpret_cast<bf16*>(stB1 + SBF);
    bf16*  Al   = Ah + ASZ;
    bf16*  Bh   = Al + ASZ;
    bf16*  Bl   = Bh + BSZ;

    const int bz = blockIdx.z;
    A += (long long)bz * sA;
    B += (long long)bz * sB;
    C += (long long)bz * sC;
    if (MODE == 3) C += (long long)blockIdx.x * sKS;
    if (MODE == 1 || MODE == 2) ep += (long long)bz * sEp;

    const int m0 = blockIdx.y * 128;
    const int n0 = (MODE == 3) ? 0 : blockIdx.x * BN;
    const int tid = threadIdx.x, l = tid & 31, wid = tid >> 5;
    constexpr int WN = BN / 2;
    constexpr int NT = WN / 8;
    const int wm = wid & 3, wn = wid >> 2;
    const int rmw = wm * 32;
    const int nbw = wn * WN;

    float acc[2][NT][4];
#pragma unroll
    for (int i = 0; i < 2; ++i)
#pragma unroll
        for (int j = 0; j < NT; ++j)
#pragma unroll
            for (int q = 0; q < 4; ++q) acc[i][j][q] = 0.f;

    const uint32_t baseAh = smem_u32(Ah), baseAl = smem_u32(Al);
    const uint32_t baseBh = smem_u32(Bh), baseBl = smem_u32(Bl);
    uint32_t aoff, boff;
    if (TRA) aoff = (((l & 7) + ((l >> 4) << 3)) * PA + ((l >> 3) & 1) * 8) * 2;
    else     aoff = ((l & 15) * PA + (l >> 4) * 8) * 2;
    if (TRB) boff = (((l & 7) + (((l >> 3) & 1) << 3)) * PB + ((l >> 4) << 3)) * 2;
    else     boff = (((l & 7) + ((l >> 4) << 3)) * PB + ((l >> 3) & 1) * 8) * 2;

    const int kItersAll = (K + 31) / 32;
    int kt0 = 0, kt1 = kItersAll;
    if (MODE == 3) {
        kt0 = blockIdx.x * kItersPer;
        kt1 = min(kItersAll, kt0 + kItersPer);
    }

    auto prefetch = [&](int kt, int buf) {
        const int k0 = kt * 32;
        float* sa = buf ? stA1 : stA0;
        float* sb = buf ? stB1 : stB0;
        if (TRA) pf_tr<128>(A, k0, K, m0, M, lda, sa);
        else     pf_nt(A, m0, M, lda, k0, K, sa);
        if (TRB) pf_tr<BN>(B, k0, K, n0, N, ldb, sb);
        else     pf_nt(B, n0, N, ldb, k0, K, sb);
        asm volatile("cp.async.commit_group;" ::: "memory");
    };

    if (kt0 < kt1) {
        prefetch(kt0, 0);
        for (int kt = kt0; kt < kt1; ++kt) {
            const int cur = (kt - kt0) & 1;
            if (kt + 1 < kt1) {
                prefetch(kt + 1, cur ^ 1);
                asm volatile("cp.async.wait_group 1;" ::: "memory");
            } else {
                asm volatile("cp.async.wait_group 0;" ::: "memory");
            }
            __syncthreads();
            if (TRA) cvt_tr<128, 136>(cur ? stA1 : stA0, Ah, Al);
            else     cvt_nt(cur ? stA1 : stA0, Ah, Al);
            if (TRB) cvt_tr<BN, BN + 8>(cur ? stB1 : stB0, Bh, Bl);
            else     cvt_nt(cur ? stB1 : stB0, Bh, Bl);
            __syncthreads();
#pragma unroll
            for (int ks = 0; ks < 2; ++ks) {
                uint32_t ah[2][4], al2[2][4];
#pragma unroll
                for (int mt = 0; mt < 2; ++mt) {
                    const int rm = rmw + mt * 16;
                    const uint32_t rel = TRA ? (uint32_t)((ks * 16 * PA + rm) * 2)
                                             : (uint32_t)((rm * PA + ks * 16) * 2);
                    if (TRA) { ldm4t(ah[mt], baseAh + rel + aoff); ldm4t(al2[mt], baseAl + rel + aoff); }
                    else     { ldm4 (ah[mt], baseAh + rel + aoff); ldm4 (al2[mt], baseAl + rel + aoff); }
                }
                uint32_t bh[NT][2], bl2[NT][2];
#pragma unroll
                for (int np = 0; np < NT / 2; ++np) {
                    const int nb = nbw + np * 16;
                    const uint32_t rel = TRB ? (uint32_t)((ks * 16 * PB + nb) * 2)
                                             : (uint32_t)((nb * PB + ks * 16) * 2);
                    uint32_t rh[4], rl[4];
                    if (TRB) { ldm4t(rh, baseBh + rel + boff); ldm4t(rl, baseBl + rel + boff); }
                    else     { ldm4 (rh, baseBh + rel + boff); ldm4 (rl, baseBl + rel + boff); }
                    bh[2 * np][0] = rh[0]; bh[2 * np][1] = rh[1];
                    bh[2 * np + 1][0] = rh[2]; bh[2 * np + 1][1] = rh[3];
                    bl2[2 * np][0] = rl[0]; bl2[2 * np][1] = rl[1];
                    bl2[2 * np + 1][0] = rl[2]; bl2[2 * np + 1][1] = rl[3];
                }
#pragma unroll
                for (int mt = 0; mt < 2; ++mt)
#pragma unroll
                    for (int nt = 0; nt < NT; ++nt) {
                        mma16816(acc[mt][nt], ah[mt],  bh[nt]);
                        mma16816(acc[mt][nt], ah[mt],  bl2[nt]);
                        mma16816(acc[mt][nt], al2[mt], bh[nt]);
                    }
            }
            __syncthreads();
        }
    }

#pragma unroll
    for (int mt = 0; mt < 2; ++mt)
#pragma unroll
        for (int nt = 0; nt < NT; ++nt)
#pragma unroll
            for (int half = 0; half < 2; ++half) {
                const int m = m0 + rmw + mt * 16 + (l >> 2) + half * 8;
                const int n = n0 + nbw + nt * 8 + (l & 3) * 2;
                if (m >= M) continue;
                float v0 = acc[mt][nt][half * 2 + 0];
                float v1 = acc[mt][nt][half * 2 + 1];
                if (MODE == 1) {
                    if (n < N)     v0 += ep[n];
                    if (n + 1 < N) v1 += ep[n + 1];
                }
                if (MODE == 2) {
                    if (n < N)     v0 *= scale * ep[(long long)m * Tdim + n];
                    if (n + 1 < N) v1 *= scale * ep[(long long)m * Tdim + n + 1];
                }
                if (n + 1 < N) {
                    *reinterpret_cast<float2*>(C + (long long)m * ldc + n) = make_float2(v0, v1);
                } else if (n < N) {
                    C[(long long)m * ldc + n] = v0;
                }
            }
}

// ------------------- elementwise kernels -------------------------------------
__global__ void pack_wb(const float* Wq, const float* Wk, const float* Wv,
                        const float* bq, const float* bk, const float* bv)
{
    const int i = blockIdx.x * 256 + threadIdx.x;
    const int WW = Ddim * Ddim;
    if (i < WW) {
        g_Wcat[i] = Wq[i];
        g_Wcat[WW + i] = Wk[i];
        g_Wcat[2 * WW + i] = Wv[i];
    }
    if (i < Ddim) {
        g_bcat[i] = bq[i];
        g_bcat[Ddim + i] = bk[i];
        g_bcat[2 * Ddim + i] = bv[i];
    }
}

__global__ void scatter_qkv()
{
    const int idx = blockIdx.x * 256 + threadIdx.x;
    if (idx >= BE * TDE) return;
    const int g = idx / TDE, f = idx % TDE;
    const int b = g >> 3, e = g & 7;
    const int tt = f % Tdim, j = f / Tdim;
    const long long src = (long long)(b * Tdim + tt) * Ddim + e * DE + j;
    const float yq = g_Y[src];
    const float yk = g_Y[(long long)BT * Ddim + src];
    const float yv = g_Y[2ll * BT * Ddim + src];
    g_Q[idx] = 1.2f / (1.f + expf(-1.6f * yq));
    g_K[idx] = 1.2f / (1.f + expf(-1.6f * yk));
    g_V[idx] = yv;
}

__global__ void reduceK(const float* __restrict__ src, float* __restrict__ dst)
{
    const int N4 = BE * TDE / 4;
    const int i = blockIdx.x * 256 + threadIdx.x;
    if (i >= N4) return;
    const float4* p = reinterpret_cast<const float4*>(src);
    float4 r = p[i];
#pragma unroll
    for (int s = 1; s < KSPLIT; ++s) {
        float4 a = p[(long long)s * N4 + i];
        r.x += a.x; r.y += a.y; r.z += a.z; r.w += a.w;
    }
    reinterpret_cast<float4*>(dst)[i] = r;
}

__global__ void gather_x()
{
    const int idx = blockIdx.x * 256 + threadIdx.x;
    if (idx >= BT * Ddim) return;
    const int b = idx / (Tdim * Ddim);
    const int rem = idx % (Tdim * Ddim);
    const int t = rem / Ddim, d = rem % Ddim;
    const int g = b * Edim + (d >> 6);
    g_X[idx] = g_O[((long long)g * Tdim + t) * DE + (d & 63)];
}

// ------------------- launch --------------------------------------------------
static inline int smem_sz(int BN, bool TRA, bool TRB)
{
    const int ASZ = TRA ? 32 * 136 : 128 * 40;
    const int BSZ = TRB ? 32 * (BN + 8) : BN * 40;
    const int SAF = TRA ? 32 * 129 : 128 * 36;
    const int SBF = TRB ? 32 * (BN + 1) : BN * 36;
    return (SAF + SBF) * 2 * 4 + (ASZ + BSZ) * 2 * 2;
}

extern "C" void kernel_launch(void* const* d_in, const int* in_sizes, int n_in,
                              void* d_out, int out_size)
{
    const float* input  = (const float*)d_in[0];
    const float* Wq     = (const float*)d_in[1];
    const float* bq     = (const float*)d_in[2];
    const float* Wk     = (const float*)d_in[3];
    const float* bk     = (const float*)d_in[4];
    const float* Wv     = (const float*)d_in[5];
    const float* bv     = (const float*)d_in[6];
    const float* Wo     = (const float*)d_in[7];
    const float* bo     = (const float*)d_in[8];
    const float* punish = (const float*)d_in[9];
    const float* orth   = (const float*)d_in[10];
    float* out = (float*)d_out;

    float *Y, *Wcat, *bcat, *Q, *Kp, *V, *W2p, *W2, *S, *Op, *O, *X;
    cudaGetSymbolAddress((void**)&Y,    g_Y);
    cudaGetSymbolAddress((void**)&Wcat, g_Wcat);
    cudaGetSymbolAddress((void**)&bcat, g_bcat);
    cudaGetSymbolAddress((void**)&Q,    g_Q);
    cudaGetSymbolAddress((void**)&Kp,   g_K);
    cudaGetSymbolAddress((void**)&V,    g_V);
    cudaGetSymbolAddress((void**)&W2p,  g_W2p);
    cudaGetSymbolAddress((void**)&W2,   g_W2);
    cudaGetSymbolAddress((void**)&S,    g_S);
    cudaGetSymbolAddress((void**)&Op,   g_Op);
    cudaGetSymbolAddress((void**)&O,    g_O);
    cudaGetSymbolAddress((void**)&X,    g_X);

    const float inv_sqrt_T = 1.0f / sqrtf((float)Tdim);
    const int WW = Ddim * Ddim;

    const int SM_P  = smem_sz(128, false, false);  // proj / S / out
    const int SM_W2 = smem_sz(64,  true,  true);
    const int SM_O  = smem_sz(64,  false, true);

    cudaFuncSetAttribute(mma_gemm<128, 0, 0, 1>,
                         cudaFuncAttributeMaxDynamicSharedMemorySize, SM_P);
    cudaFuncSetAttribute(mma_gemm<128, 0, 0, 2>,
                         cudaFuncAttributeMaxDynamicSharedMemorySize, SM_P);
    cudaFuncSetAttribute(mma_gemm<64, 1, 1, 3>,
                         cudaFuncAttributeMaxDynamicSharedMemorySize, SM_W2);
    cudaFuncSetAttribute(mma_gemm<64, 0, 1, 3>,
                         cudaFuncAttributeMaxDynamicSharedMemorySize, SM_O);

    const int kPer = (((Tdim + 31) / 32) + KSPLIT - 1) / KSPLIT;   // 52/8 -> 7

    // 0) pack Q/K/V weights
    pack_wb<<<(WW + 255) / 256, 256>>>(Wq, Wk, Wv, bq, bk, bv);

    // 1) projections: Y[z] = input @ W[z]^T + b[z]
    mma_gemm<128, 0, 0, 1><<<dim3(4, 26, 3), 256, SM_P>>>(
        input, Wcat, Y, BT, Ddim, Ddim, Ddim, Ddim, Ddim,
        0ll, (long long)WW, (long long)BT * Ddim, bcat, (long long)Ddim, 0.f, 0, 0ll);

    // 2) reshape + sigmoid
    scatter_qkv<<<(BE * TDE + 255) / 256, 256>>>();

    // 3) W2 partials = orth^T @ V  (split-K x8, cp.async pipelined), reduce
    mma_gemm<64, 1, 1, 3><<<dim3(KSPLIT, 13, BE), 256, SM_W2>>>(
        orth, V, W2p, Tdim, DE, Tdim, Tdim, DE, DE,
        TT, (long long)TDE, (long long)TDE, nullptr, 0ll, 0.f,
        kPer, (long long)BE * TDE);
    reduceK<<<(BE * TDE / 4 + 255) / 256, 256>>>(W2p, W2);

    // 4) S = (Q K^T) * scale * punish  -> fp32, padded stride TSP
    mma_gemm<128, 0, 0, 2><<<dim3(13, 13, BE), 256, SM_P>>>(
        Q, Kp, S, Tdim, Tdim, DE, DE, DE, TSP,
        (long long)TDE, (long long)TDE, (long long)Tdim * TSP,
        punish, 0ll, inv_sqrt_T, 0, 0ll);

    // 5) O partials = S @ W2  (split-K x8), reduce
    mma_gemm<64, 0, 1, 3><<<dim3(KSPLIT, 13, BE), 256, SM_O>>>(
        S, W2, Op, Tdim, DE, Tdim, TSP, DE, DE,
        (long long)Tdim * TSP, (long long)TDE, (long long)TDE, nullptr, 0ll, 0.f,
        kPer, (long long)BE * TDE);
    reduceK<<<(BE * TDE / 4 + 255) / 256, 256>>>(Op, O);

    // 6) inverse reshape
    gather_x<<<(BT * Ddim + 255) / 256, 256>>>();

    // 7) out = X @ Wo^T + bo
    mma_gemm<128, 0, 0, 1><<<dim3(4, 26, 1), 256, SM_P>>>(
        X, Wo, out, BT, Ddim, Ddim, Ddim, Ddim, Ddim,
        0ll, 0ll, 0ll, bo, 0ll, 0.f, 0, 0ll);
}